// round 10
// baseline (speedup 1.0000x reference)
#include <cuda_runtime.h>
#include <cuda_bf16.h>
#include <cstdint>

#define N_NODES 100000
#define N_EDGES 1600000
#define N_HOPS 3
#define D_FEAT 128
#define D_HID 256
#define NUM_GRAPHS 64
#define TM 128
#define NT_TILES ((N_NODES + TM - 1) / TM)   // 782
#define GRID_FUSED 148
#define THREADS_FUSED 512

// ---- dynamic smem layout (bytes) ----
#define OFF_B1 0                     // 1024  (b1 fp32)
#define OFF_XH 1024                  // 32768 (X hi bf16 [128][128] swizzled)
#define OFF_XL (OFF_XH + 32768)      // 32768 (X lo)
#define OFF_RH (OFF_XL + 32768)      // 32768 (R hi, current half)
#define OFF_RL (OFF_RH + 32768)      // 32768 (R lo)
#define OFF_WH (OFF_RL + 32768)      // 32768 (W hi, current half)
#define OFF_WL (OFF_WH + 32768)      // 32768 (W lo)
#define OFF_CH (OFF_WL + 32768)      // 16384 (C' hi [64][128])
#define OFF_CL (OFF_CH + 16384)      // 16384 (C' lo)
#define SMEM_TOTAL (OFF_CL + 16384)  // 230400

// Scratch (device globals; no runtime allocation allowed)
__device__ __align__(16) float g_C[(size_t)N_NODES * NUM_GRAPHS];  // 25.6 MB
__device__ __align__(16) float g_CR[NUM_GRAPHS * D_HID];
__device__ float g_rowsum[NUM_GRAPHS];
__device__ int g_idx64;
__device__ unsigned char g_b8[N_NODES];
// W1 bf16 images, pre-swizzled: [half][hi|lo][k 128][n 128]
__device__ __align__(16) unsigned char g_W1img[131072];

// ---------------- helpers ----------------
__device__ __forceinline__ uint32_t smem_u32(const void* p) {
    uint32_t a;
    asm("{ .reg .u64 t; cvta.to.shared.u64 t, %1; cvt.u32.u64 %0, t; }" : "=r"(a) : "l"(p));
    return a;
}
// swizzled byte offset within a [rows][256B] tile; cb = byte col in [0,256)
__device__ __forceinline__ uint32_t swz(uint32_t r, uint32_t cb) {
    return r * 256u + (((cb) & ~15u) ^ ((r & 7u) << 4)) + (cb & 15u);
}
__device__ __forceinline__ void ldsm4(uint32_t* r, uint32_t addr) {
    asm volatile("ldmatrix.sync.aligned.m8n8.x4.shared.b16 {%0,%1,%2,%3}, [%4];"
                 : "=r"(r[0]), "=r"(r[1]), "=r"(r[2]), "=r"(r[3]) : "r"(addr));
}
__device__ __forceinline__ void ldsm4t(uint32_t* r, uint32_t addr) {
    asm volatile("ldmatrix.sync.aligned.m8n8.x4.trans.shared.b16 {%0,%1,%2,%3}, [%4];"
                 : "=r"(r[0]), "=r"(r[1]), "=r"(r[2]), "=r"(r[3]) : "r"(addr));
}
__device__ __forceinline__ void mma_bf16(float* c, const uint32_t* a, const uint32_t* b) {
    asm volatile("mma.sync.aligned.m16n8k16.row.col.f32.bf16.bf16.f32 "
                 "{%0,%1,%2,%3}, {%4,%5,%6,%7}, {%8,%9}, {%0,%1,%2,%3};"
                 : "+f"(c[0]), "+f"(c[1]), "+f"(c[2]), "+f"(c[3])
                 : "r"(a[0]), "r"(a[1]), "r"(a[2]), "r"(a[3]), "r"(b[0]), "r"(b[1]));
}
__device__ __forceinline__ uint32_t pkbf2(float a, float b) {
    __nv_bfloat162 t = __floats2bfloat162_rn(a, b);
    return *reinterpret_cast<uint32_t*>(&t);
}
__device__ __forceinline__ int load_index(const void* p, long long i, int is64) {
    if (is64) return (int)((const long long*)p)[i];
    return ((const int*)p)[i];
}

// ---------- kernel: detect int width + zero accumulators ----------
__global__ void k_detect(const unsigned int* __restrict__ ei_words) {
    int t = threadIdx.x;
    if (t == 0) {
        unsigned int acc = 0;
#pragma unroll
        for (int i = 0; i < 64; i++) acc |= ei_words[2 * i + 1];
        g_idx64 = (acc == 0u) ? 1 : 0;
    }
    for (int i = t; i < NUM_GRAPHS * D_HID; i += 256) g_CR[i] = 0.f;
    if (t < NUM_GRAPHS) g_rowsum[t] = 0.f;
}

// ---------- batch -> uint8 + rowsum pw0 part (smem histogram) ----------
__global__ void k_prep(const void* __restrict__ batch, const float* __restrict__ prop_w) {
    __shared__ float h[NUM_GRAPHS];
    int t = threadIdx.x;
    if (t < NUM_GRAPHS) h[t] = 0.f;
    __syncthreads();
    int is64 = g_idx64;
    float pw0 = prop_w[0];
    int i = blockIdx.x * blockDim.x + t;
    if (i < N_NODES) {
        int g = load_index(batch, i, is64) & (NUM_GRAPHS - 1);
        g_b8[i] = (unsigned char)g;
        atomicAdd(&h[g], pw0);
    }
    __syncthreads();
    if (t < NUM_GRAPHS && h[t] != 0.f) atomicAdd(&g_rowsum[t], h[t]);
}

// W1 -> pre-swizzled bf16 hi/lo images per half: layout [k][n] (B of GEMM1)
__global__ void k_prepW(const float* __restrict__ w1) {
    int idx = blockIdx.x * blockDim.x + threadIdx.x;  // 2*128*128
    if (idx >= 2 * 128 * 128) return;
    int half = idx >> 14;
    int k = (idx >> 7) & 127;
    int n = idx & 127;
    float v = w1[(size_t)k * D_HID + half * 128 + n];
    __nv_bfloat16 hi = __float2bfloat16(v);
    __nv_bfloat16 lo = __float2bfloat16(v - __bfloat162float(hi));
    uint32_t off = swz((uint32_t)k, (uint32_t)n * 2);
    *reinterpret_cast<__nv_bfloat16*>(g_W1img + half * 65536 + off) = hi;
    *reinterpret_cast<__nv_bfloat16*>(g_W1img + half * 65536 + 32768 + off) = lo;
}

__global__ void k_initC(const float* __restrict__ prop_w) {
    int idx = blockIdx.x * blockDim.x + threadIdx.x;
    if (idx >= N_NODES * 16) return;
    int n = idx >> 4;
    int cb = (idx & 15) * 4;
    int g = g_b8[n];
    float pw0 = prop_w[0];
    float4 v = make_float4(0.f, 0.f, 0.f, 0.f);
    if (g >= cb && g < cb + 4) ((float*)&v)[g - cb] = pw0;
    *reinterpret_cast<float4*>(&g_C[(size_t)n * NUM_GRAPHS + cb]) = v;
}

// ---------- edge scatter into C + rowsum edge part (smem histogram) ----------
__global__ void k_edges(const void* __restrict__ ei, const float* __restrict__ ew,
                        const float* __restrict__ prop_w) {
    __shared__ float h[NUM_GRAPHS];
    int t = threadIdx.x;
    if (t < NUM_GRAPHS) h[t] = 0.f;
    __syncthreads();
    float pw0 = prop_w[1], pw1 = prop_w[2], pw2 = prop_w[3];
    int is64 = g_idx64;
    const long long total = (long long)N_HOPS * N_EDGES;
    long long stride = (long long)gridDim.x * blockDim.x;
    for (long long idx = (long long)blockIdx.x * blockDim.x + t; idx < total;
         idx += stride) {
        int hop = (int)(idx / N_EDGES);
        long long r = idx - (long long)hop * N_EDGES;
        long long base = (long long)hop * 2 * N_EDGES;
        int s = load_index(ei, base + r, is64);
        int d = load_index(ei, base + N_EDGES + r, is64);
        s = min(max(s, 0), N_NODES - 1);
        d = min(max(d, 0), N_NODES - 1);
        float w = ew[(size_t)hop * N_EDGES + r];
        float pw = (hop == 0) ? pw0 : (hop == 1) ? pw1 : pw2;
        int g = g_b8[d];
        float val = pw * w;
        atomicAdd(&g_C[(size_t)s * NUM_GRAPHS + g], val);
        atomicAdd(&h[g], val);
    }
    __syncthreads();
    if (t < NUM_GRAPHS && h[t] != 0.f) atomicAdd(&g_rowsum[t], h[t]);
}

// ---------- fused mma.sync kernel (16 warps, X staged once/tile) ----------
__global__ void __launch_bounds__(THREADS_FUSED, 1)
k_fused(const float* __restrict__ x, const float* __restrict__ b1) {
    extern __shared__ char sm[];
    const uint32_t smb = smem_u32(sm);
    float* sb1 = reinterpret_cast<float*>(sm + OFF_B1);

    const int t = threadIdx.x;
    const int lane = t & 31;
    const int w = t >> 5;  // 0..15

    if (t < 256) sb1[t] = b1[t];

    // GEMM1: warp = m32 (nodes) x n32 (hid cols within half)
    const int m1base = (w & 3) * 32;
    const int n1base = (w >> 2) * 32;
    // GEMM2: warp = m16 (graphs) x n32 (hid cols within half)
    const int m2base = (w & 3) * 16;
    const int n2base = (w >> 2) * 32;

    const uint32_t lr = lane & 15;
    const uint32_t lc = (lane >> 4) * 16;
    const int qrow = lane >> 2;
    const int qcol = (lane & 3) * 2;

    float accG[2][4][4];  // [half][nt][reg] persistent
#pragma unroll
    for (int h = 0; h < 2; h++)
#pragma unroll
        for (int b = 0; b < 4; b++)
#pragma unroll
            for (int c = 0; c < 4; c++) accG[h][b][c] = 0.f;

    // W copy helper indices: 512 threads x 8 uint4 = 64 KB
    const uint4* wsrc0 = reinterpret_cast<const uint4*>(g_W1img);
    const uint4* wsrc1 = reinterpret_cast<const uint4*>(g_W1img + 65536);
    uint4* wdst = reinterpret_cast<uint4*>(sm + OFF_WH);

    for (int tile = blockIdx.x; tile < NT_TILES; tile += gridDim.x) {
        __syncthreads();  // previous tile's GEMM1/GEMM2 reads done
        // ---- stage X tile -> bf16 hi/lo (swizzled), ONCE per tile ----
        {
            int row = t >> 2;
            int c0 = (t & 3) * 32;
            int node = tile * TM + row;
            bool valid = node < N_NODES;
            const float* xr = x + (size_t)node * D_FEAT + c0;
#pragma unroll
            for (int i = 0; i < 8; i++) {
                float4 f = valid ? *reinterpret_cast<const float4*>(xr + i * 4)
                                 : make_float4(0.f, 0.f, 0.f, 0.f);
                float l0 = f.x - __bfloat162float(__float2bfloat16(f.x));
                float l1 = f.y - __bfloat162float(__float2bfloat16(f.y));
                float l2 = f.z - __bfloat162float(__float2bfloat16(f.z));
                float l3 = f.w - __bfloat162float(__float2bfloat16(f.w));
                uint2 hv = make_uint2(pkbf2(f.x, f.y), pkbf2(f.z, f.w));
                uint2 lv = make_uint2(pkbf2(l0, l1), pkbf2(l2, l3));
                uint32_t off = swz((uint32_t)row, (uint32_t)(c0 + i * 4) * 2);
                *reinterpret_cast<uint2*>(sm + OFF_XH + off) = hv;
                *reinterpret_cast<uint2*>(sm + OFF_XL + off) = lv;
            }
        }
        // ---- stage C' (transposed, hi/lo) once per tile ----
        {
            int node = t >> 2;
            int g0 = (t & 3) * 16;
            int gn = tile * TM + node;
            bool valid = gn < N_NODES;
            const float* cr = g_C + (size_t)gn * NUM_GRAPHS + g0;
#pragma unroll
            for (int i = 0; i < 4; i++) {
                float4 f = valid ? *reinterpret_cast<const float4*>(cr + i * 4)
                                 : make_float4(0.f, 0.f, 0.f, 0.f);
#pragma unroll
                for (int j = 0; j < 4; j++) {
                    float v = ((const float*)&f)[j];
                    __nv_bfloat16 hi = __float2bfloat16(v);
                    __nv_bfloat16 lo = __float2bfloat16(v - __bfloat162float(hi));
                    uint32_t off = swz((uint32_t)(g0 + i * 4 + j), (uint32_t)node * 2);
                    *reinterpret_cast<__nv_bfloat16*>(sm + OFF_CH + off) = hi;
                    *reinterpret_cast<__nv_bfloat16*>(sm + OFF_CL + off) = lo;
                }
            }
        }
        // ---- copy W half0 image into smem ----
#pragma unroll
        for (int i = 0; i < 8; i++) wdst[t + i * THREADS_FUSED] = wsrc0[t + i * THREADS_FUSED];
        __syncthreads();

#pragma unroll 1
        for (int half = 0; half < 2; half++) {
            // ---- GEMM1: acc1 = X @ W(half) ----
            float acc1[2][4][4];
#pragma unroll
            for (int a = 0; a < 2; a++)
#pragma unroll
                for (int b = 0; b < 4; b++)
#pragma unroll
                    for (int c = 0; c < 4; c++) acc1[a][b][c] = 0.f;
#pragma unroll 1
            for (int pass = 0; pass < 3; pass++) {
                uint32_t Ab = smb + (pass == 2 ? OFF_XL : OFF_XH);
                uint32_t Bb = smb + (pass == 1 ? OFF_WL : OFF_WH);
#pragma unroll
                for (int k0 = 0; k0 < 128; k0 += 16) {
                    uint32_t a[2][4], b[2][4];
#pragma unroll
                    for (int mg = 0; mg < 2; mg++)
                        ldsm4(a[mg], Ab + swz(m1base + mg * 16 + lr, k0 * 2 + lc));
#pragma unroll
                    for (int nt2 = 0; nt2 < 2; nt2++)
                        ldsm4t(b[nt2], Bb + swz(k0 + lr, (n1base + nt2 * 16) * 2 + lc));
#pragma unroll
                    for (int mg = 0; mg < 2; mg++)
#pragma unroll
                        for (int nt = 0; nt < 4; nt++)
                            mma_bf16(acc1[mg][nt], a[mg], &b[nt >> 1][(nt & 1) * 2]);
                }
            }
            // ---- bias + relu + split -> R buffers ----
#pragma unroll
            for (int mg = 0; mg < 2; mg++) {
                int row0 = m1base + mg * 16 + qrow;
#pragma unroll
                for (int nt = 0; nt < 4; nt++) {
                    int col = n1base + nt * 8 + qcol;
                    float bias0 = sb1[half * 128 + col];
                    float bias1 = sb1[half * 128 + col + 1];
#pragma unroll
                    for (int rh = 0; rh < 2; rh++) {
                        float v0 = fmaxf(acc1[mg][nt][rh * 2 + 0] + bias0, 0.f);
                        float v1 = fmaxf(acc1[mg][nt][rh * 2 + 1] + bias1, 0.f);
                        float w0 = v0 - __bfloat162float(__float2bfloat16(v0));
                        float w1v = v1 - __bfloat162float(__float2bfloat16(v1));
                        uint32_t off = swz((uint32_t)(row0 + rh * 8), (uint32_t)col * 2);
                        *reinterpret_cast<uint32_t*>(sm + OFF_RH + off) = pkbf2(v0, v1);
                        *reinterpret_cast<uint32_t*>(sm + OFF_RL + off) = pkbf2(w0, w1v);
                    }
                }
            }
            __syncthreads();  // R ready; all warps done reading W

            // ---- GEMM2: accG[half] += C' @ R ; overlap: copy W half1 ----
#pragma unroll 1
            for (int pass = 0; pass < 3; pass++) {
                uint32_t Ab = smb + (pass == 2 ? OFF_CL : OFF_CH);
                uint32_t Bb = smb + (pass == 1 ? OFF_RL : OFF_RH);
#pragma unroll
                for (int k0 = 0; k0 < 128; k0 += 16) {
                    uint32_t a[4], b[2][4];
                    ldsm4(a, Ab + swz(m2base + lr, k0 * 2 + lc));
#pragma unroll
                    for (int nt2 = 0; nt2 < 2; nt2++)
                        ldsm4t(b[nt2], Bb + swz(k0 + lr, (n2base + nt2 * 16) * 2 + lc));
#pragma unroll
                    for (int nt = 0; nt < 4; nt++)
                        mma_bf16(accG[half][nt], a, &b[nt >> 1][(nt & 1) * 2]);
                }
            }
            if (half == 0) {
                // copy W half1 (W buffer free: GEMM1 h0 readers passed the sync)
#pragma unroll
                for (int i = 0; i < 8; i++)
                    wdst[t + i * THREADS_FUSED] = wsrc1[t + i * THREADS_FUSED];
                __syncthreads();  // W h1 ready; GEMM2 h0 done (R free for h1 split)
            }
        }  // half
    }  // tile

    // ---- drain persistent accumulators ----
#pragma unroll
    for (int half = 0; half < 2; half++)
#pragma unroll
        for (int nt = 0; nt < 4; nt++) {
            int gr = m2base + qrow;
            int col = half * 128 + n2base + nt * 8 + qcol;
            atomicAdd(&g_CR[gr * D_HID + col], accG[half][nt][0]);
            atomicAdd(&g_CR[gr * D_HID + col + 1], accG[half][nt][1]);
            atomicAdd(&g_CR[(gr + 8) * D_HID + col], accG[half][nt][2]);
            atomicAdd(&g_CR[(gr + 8) * D_HID + col + 1], accG[half][nt][3]);
        }
}

// ---------- final: pooled = CR @ w2 + rowsum*b2, log_softmax ----------
__global__ void k_final(const float* __restrict__ w2, const float* __restrict__ b2,
                        float* __restrict__ out) {
    int g = blockIdx.x;
    int f = threadIdx.x;
    float v = g_rowsum[g] * b2[f];
    const float* cr = g_CR + g * D_HID;
#pragma unroll 8
    for (int k = 0; k < D_HID; k++) v += cr[k] * w2[k * D_FEAT + f];

    __shared__ float sh[D_FEAT];
    sh[f] = v;
    __syncthreads();
    for (int s = D_FEAT / 2; s > 0; s >>= 1) {
        if (f < s) sh[f] = fmaxf(sh[f], sh[f + s]);
        __syncthreads();
    }
    float m = sh[0];
    __syncthreads();
    sh[f] = expf(v - m);
    __syncthreads();
    for (int s = D_FEAT / 2; s > 0; s >>= 1) {
        if (f < s) sh[f] += sh[f + s];
        __syncthreads();
    }
    float lse = logf(sh[0]);
    out[g * D_FEAT + f] = v - m - lse;
}

extern "C" void kernel_launch(void* const* d_in, const int* in_sizes, int n_in,
                              void* d_out, int out_size) {
    const float* x = (const float*)d_in[0];
    const void* ei = d_in[1];
    const float* ew = (const float*)d_in[2];
    const void* batch = d_in[3];
    const float* w1 = (const float*)d_in[4];
    const float* b1 = (const float*)d_in[5];
    const float* w2 = (const float*)d_in[6];
    const float* b2 = (const float*)d_in[7];
    const float* pw = (const float*)d_in[8];
    float* out = (float*)d_out;

    cudaFuncSetAttribute(k_fused, cudaFuncAttributeMaxDynamicSharedMemorySize, SMEM_TOTAL);

    k_detect<<<1, 256>>>((const unsigned int*)ei);
    k_prep<<<(N_NODES + 255) / 256, 256>>>(batch, pw);
    k_prepW<<<128, 256>>>(w1);
    k_initC<<<(N_NODES * 16 + 255) / 256, 256>>>(pw);
    k_edges<<<4096, 256>>>(ei, ew, pw);
    k_fused<<<GRID_FUSED, THREADS_FUSED, SMEM_TOTAL>>>(x, b1);
    k_final<<<NUM_GRAPHS, D_FEAT>>>(w2, b2, out);
}

// round 11
// speedup vs baseline: 1.0927x; 1.0927x over previous
#include <cuda_runtime.h>
#include <cuda_fp16.h>
#include <cstdint>

#define N_NODES 100000
#define N_EDGES 1600000
#define N_HOPS 3
#define D_FEAT 128
#define D_HID 256
#define NUM_GRAPHS 64
#define TM 128
#define NT_TILES ((N_NODES + TM - 1) / TM)   // 782
#define GRID_FUSED 148
#define THREADS_FUSED 512

// ---- dynamic smem layout (bytes) ----
#define OFF_B1 0                     // 1024  (b1 fp32)
#define OFF_XH 1024                  // 32768 (X hi fp16 [128][128] swizzled)
#define OFF_XL (OFF_XH + 32768)      // 32768 (X lo fp16)
#define OFF_RH (OFF_XL + 32768)      // 32768 (R hi fp16, current half)
#define OFF_RL (OFF_RH + 32768)      // 32768 (R lo fp16)
#define OFF_W  (OFF_RL + 32768)      // 65536 (W fp16 single image, both halves)
#define OFF_CH (OFF_W + 65536)       // 16384 (C' hi fp16 [64][128])
#define OFF_CL (OFF_CH + 16384)      // 16384 (C' lo fp16)
#define SMEM_TOTAL (OFF_CL + 16384)  // 230400

// Scratch (device globals; no runtime allocation allowed)
__device__ __align__(16) float g_C[(size_t)N_NODES * NUM_GRAPHS];  // 25.6 MB
__device__ __align__(16) float g_CR[NUM_GRAPHS * D_HID];
__device__ float g_rowsum[NUM_GRAPHS];
__device__ int g_idx64;
__device__ unsigned char g_b8[N_NODES];
// W1 fp16 image, pre-swizzled: [half][k 128][n 128]
__device__ __align__(16) unsigned char g_W1img[65536];

// ---------------- helpers ----------------
__device__ __forceinline__ uint32_t smem_u32(const void* p) {
    uint32_t a;
    asm("{ .reg .u64 t; cvta.to.shared.u64 t, %1; cvt.u32.u64 %0, t; }" : "=r"(a) : "l"(p));
    return a;
}
// swizzled byte offset within a [rows][256B] tile; cb = byte col in [0,256)
__device__ __forceinline__ uint32_t swz(uint32_t r, uint32_t cb) {
    return r * 256u + (((cb) & ~15u) ^ ((r & 7u) << 4)) + (cb & 15u);
}
__device__ __forceinline__ void ldsm4(uint32_t* r, uint32_t addr) {
    asm volatile("ldmatrix.sync.aligned.m8n8.x4.shared.b16 {%0,%1,%2,%3}, [%4];"
                 : "=r"(r[0]), "=r"(r[1]), "=r"(r[2]), "=r"(r[3]) : "r"(addr));
}
__device__ __forceinline__ void ldsm4t(uint32_t* r, uint32_t addr) {
    asm volatile("ldmatrix.sync.aligned.m8n8.x4.trans.shared.b16 {%0,%1,%2,%3}, [%4];"
                 : "=r"(r[0]), "=r"(r[1]), "=r"(r[2]), "=r"(r[3]) : "r"(addr));
}
__device__ __forceinline__ void mma_fp16(float* c, const uint32_t* a, const uint32_t* b) {
    asm volatile("mma.sync.aligned.m16n8k16.row.col.f32.f16.f16.f32 "
                 "{%0,%1,%2,%3}, {%4,%5,%6,%7}, {%8,%9}, {%0,%1,%2,%3};"
                 : "+f"(c[0]), "+f"(c[1]), "+f"(c[2]), "+f"(c[3])
                 : "r"(a[0]), "r"(a[1]), "r"(a[2]), "r"(a[3]), "r"(b[0]), "r"(b[1]));
}
__device__ __forceinline__ uint32_t pkhf2(float a, float b) {
    __half2 t = __floats2half2_rn(a, b);
    return *reinterpret_cast<uint32_t*>(&t);
}
__device__ __forceinline__ int load_index(const void* p, long long i, int is64) {
    if (is64) return (int)((const long long*)p)[i];
    return ((const int*)p)[i];
}

// ---------- kernel: detect int width + zero accumulators ----------
__global__ void k_detect(const unsigned int* __restrict__ ei_words) {
    int t = threadIdx.x;
    if (t == 0) {
        unsigned int acc = 0;
#pragma unroll
        for (int i = 0; i < 64; i++) acc |= ei_words[2 * i + 1];
        g_idx64 = (acc == 0u) ? 1 : 0;
    }
    for (int i = t; i < NUM_GRAPHS * D_HID; i += 256) g_CR[i] = 0.f;
    if (t < NUM_GRAPHS) g_rowsum[t] = 0.f;
}

// ---------- batch -> uint8 + rowsum pw0 part (smem histogram) ----------
__global__ void k_prep(const void* __restrict__ batch, const float* __restrict__ prop_w) {
    __shared__ float h[NUM_GRAPHS];
    int t = threadIdx.x;
    if (t < NUM_GRAPHS) h[t] = 0.f;
    __syncthreads();
    int is64 = g_idx64;
    float pw0 = prop_w[0];
    int i = blockIdx.x * blockDim.x + t;
    if (i < N_NODES) {
        int g = load_index(batch, i, is64) & (NUM_GRAPHS - 1);
        g_b8[i] = (unsigned char)g;
        atomicAdd(&h[g], pw0);
    }
    __syncthreads();
    if (t < NUM_GRAPHS && h[t] != 0.f) atomicAdd(&g_rowsum[t], h[t]);
}

// W1 -> pre-swizzled fp16 image per half: layout [k][n] (B of GEMM1)
__global__ void k_prepW(const float* __restrict__ w1) {
    int idx = blockIdx.x * blockDim.x + threadIdx.x;  // 2*128*128
    if (idx >= 2 * 128 * 128) return;
    int half = idx >> 14;
    int k = (idx >> 7) & 127;
    int n = idx & 127;
    float v = w1[(size_t)k * D_HID + half * 128 + n];
    uint32_t off = swz((uint32_t)k, (uint32_t)n * 2);
    *reinterpret_cast<__half*>(g_W1img + half * 32768 + off) = __float2half_rn(v);
}

// ---------- zero C (must precede edge atomics) ----------
__global__ void k_zeroC() {
    size_t i = (size_t)blockIdx.x * blockDim.x + threadIdx.x;
    size_t stride = (size_t)gridDim.x * blockDim.x;
    float4 z = make_float4(0.f, 0.f, 0.f, 0.f);
    size_t n4 = (size_t)N_NODES * NUM_GRAPHS / 4;
    for (size_t j = i; j < n4; j += stride) reinterpret_cast<float4*>(g_C)[j] = z;
}

// ---------- edge scatter into C + rowsum edge part (smem histogram) ----------
__global__ void k_edges(const void* __restrict__ ei, const float* __restrict__ ew,
                        const float* __restrict__ prop_w) {
    __shared__ float h[NUM_GRAPHS];
    int t = threadIdx.x;
    if (t < NUM_GRAPHS) h[t] = 0.f;
    __syncthreads();
    float pw0 = prop_w[1], pw1 = prop_w[2], pw2 = prop_w[3];
    int is64 = g_idx64;
    const long long total = (long long)N_HOPS * N_EDGES;
    long long stride = (long long)gridDim.x * blockDim.x;
    for (long long idx = (long long)blockIdx.x * blockDim.x + t; idx < total;
         idx += stride) {
        int hop = (int)(idx / N_EDGES);
        long long r = idx - (long long)hop * N_EDGES;
        long long base = (long long)hop * 2 * N_EDGES;
        int s = load_index(ei, base + r, is64);
        int d = load_index(ei, base + N_EDGES + r, is64);
        s = min(max(s, 0), N_NODES - 1);
        d = min(max(d, 0), N_NODES - 1);
        float w = ew[(size_t)hop * N_EDGES + r];
        float pw = (hop == 0) ? pw0 : (hop == 1) ? pw1 : pw2;
        int g = g_b8[d];
        float val = pw * w;
        atomicAdd(&g_C[(size_t)s * NUM_GRAPHS + g], val);
        atomicAdd(&h[g], val);
    }
    __syncthreads();
    if (t < NUM_GRAPHS && h[t] != 0.f) atomicAdd(&g_rowsum[t], h[t]);
}

// ---------- fused mma.sync kernel: fp16, GEMM1 2-pass, W resident ----------
__global__ void __launch_bounds__(THREADS_FUSED, 1)
k_fused(const float* __restrict__ x, const float* __restrict__ b1,
        const float* __restrict__ prop_w) {
    extern __shared__ char sm[];
    const uint32_t smb = smem_u32(sm);
    float* sb1 = reinterpret_cast<float*>(sm + OFF_B1);

    const int t = threadIdx.x;
    const int lane = t & 31;
    const int w = t >> 5;  // 0..15
    const float pw0 = prop_w[0];

    if (t < 256) sb1[t] = b1[t];
    // stage W fp16 image (both halves, resident across tiles)
    {
        const uint4* src = reinterpret_cast<const uint4*>(g_W1img);
        uint4* dst = reinterpret_cast<uint4*>(sm + OFF_W);
#pragma unroll
        for (int i = 0; i < 8; i++) dst[t + i * THREADS_FUSED] = src[t + i * THREADS_FUSED];
    }

    // GEMM1: warp = m32 (nodes) x n32 (hid cols within half)
    const int m1base = (w & 3) * 32;
    const int n1base = (w >> 2) * 32;
    // GEMM2: warp = m16 (graphs) x n32 (hid cols within half)
    const int m2base = (w & 3) * 16;
    const int n2base = (w >> 2) * 32;

    const uint32_t lr = lane & 15;
    const uint32_t lc = (lane >> 4) * 16;
    const int qrow = lane >> 2;
    const int qcol = (lane & 3) * 2;

    float accG[2][4][4];  // [half][nt][reg] persistent
#pragma unroll
    for (int h = 0; h < 2; h++)
#pragma unroll
        for (int b = 0; b < 4; b++)
#pragma unroll
            for (int c = 0; c < 4; c++) accG[h][b][c] = 0.f;

    for (int tile = blockIdx.x; tile < NT_TILES; tile += gridDim.x) {
        __syncthreads();  // all readers of X/C/R from previous tile done
        // ---- stage X tile -> fp16 hi/lo (swizzled), once per tile ----
        {
            int row = t >> 2;
            int c0 = (t & 3) * 32;
            int node = tile * TM + row;
            bool valid = node < N_NODES;
            const float* xr = x + (size_t)node * D_FEAT + c0;
#pragma unroll
            for (int i = 0; i < 8; i++) {
                float4 f = valid ? *reinterpret_cast<const float4*>(xr + i * 4)
                                 : make_float4(0.f, 0.f, 0.f, 0.f);
                float l0 = f.x - __half2float(__float2half_rn(f.x));
                float l1 = f.y - __half2float(__float2half_rn(f.y));
                float l2 = f.z - __half2float(__float2half_rn(f.z));
                float l3 = f.w - __half2float(__float2half_rn(f.w));
                uint2 hv = make_uint2(pkhf2(f.x, f.y), pkhf2(f.z, f.w));
                uint2 lv = make_uint2(pkhf2(l0, l1), pkhf2(l2, l3));
                uint32_t off = swz((uint32_t)row, (uint32_t)(c0 + i * 4) * 2);
                *reinterpret_cast<uint2*>(sm + OFF_XH + off) = hv;
                *reinterpret_cast<uint2*>(sm + OFF_XL + off) = lv;
            }
        }
        // ---- stage C' (transposed, fp16 hi/lo), fold pw0 delta, once per tile ----
        {
            int node = t >> 2;
            int g0 = (t & 3) * 16;
            int gn = tile * TM + node;
            bool valid = gn < N_NODES;
            int gb = valid ? (int)g_b8[gn] : -1;
            const float* cr = g_C + (size_t)gn * NUM_GRAPHS + g0;
#pragma unroll
            for (int i = 0; i < 4; i++) {
                float4 f = valid ? *reinterpret_cast<const float4*>(cr + i * 4)
                                 : make_float4(0.f, 0.f, 0.f, 0.f);
#pragma unroll
                for (int j = 0; j < 4; j++) {
                    int g = g0 + i * 4 + j;
                    float v = ((const float*)&f)[j];
                    if (g == gb) v += pw0;
                    __half hi = __float2half_rn(v);
                    __half lo = __float2half_rn(v - __half2float(hi));
                    uint32_t off = swz((uint32_t)g, (uint32_t)node * 2);
                    *reinterpret_cast<__half*>(sm + OFF_CH + off) = hi;
                    *reinterpret_cast<__half*>(sm + OFF_CL + off) = lo;
                }
            }
        }
        __syncthreads();

#pragma unroll 1
        for (int half = 0; half < 2; half++) {
            // ---- GEMM1 (2 passes): acc1 = (Xh + Xl) @ W(half) ----
            float acc1[2][4][4];
#pragma unroll
            for (int a = 0; a < 2; a++)
#pragma unroll
                for (int b = 0; b < 4; b++)
#pragma unroll
                    for (int c = 0; c < 4; c++) acc1[a][b][c] = 0.f;
#pragma unroll 1
            for (int pass = 0; pass < 2; pass++) {
                uint32_t Ab = smb + (pass == 1 ? OFF_XL : OFF_XH);
                uint32_t Bb = smb + OFF_W + half * 32768;
#pragma unroll
                for (int k0 = 0; k0 < 128; k0 += 16) {
                    uint32_t a[2][4], b[2][4];
#pragma unroll
                    for (int mg = 0; mg < 2; mg++)
                        ldsm4(a[mg], Ab + swz(m1base + mg * 16 + lr, k0 * 2 + lc));
#pragma unroll
                    for (int nt2 = 0; nt2 < 2; nt2++)
                        ldsm4t(b[nt2], Bb + swz(k0 + lr, (n1base + nt2 * 16) * 2 + lc));
#pragma unroll
                    for (int mg = 0; mg < 2; mg++)
#pragma unroll
                        for (int nt = 0; nt < 4; nt++)
                            mma_fp16(acc1[mg][nt], a[mg], &b[nt >> 1][(nt & 1) * 2]);
                }
            }
            // ---- bias + relu + fp16 hi/lo split -> R buffers ----
            // (h0: prev-tile G2h1 readers passed loop-top sync; h1: G2h0 passed sync below)
#pragma unroll
            for (int mg = 0; mg < 2; mg++) {
                int row0 = m1base + mg * 16 + qrow;
#pragma unroll
                for (int nt = 0; nt < 4; nt++) {
                    int col = n1base + nt * 8 + qcol;
                    float bias0 = sb1[half * 128 + col];
                    float bias1 = sb1[half * 128 + col + 1];
#pragma unroll
                    for (int rh = 0; rh < 2; rh++) {
                        float v0 = fmaxf(acc1[mg][nt][rh * 2 + 0] + bias0, 0.f);
                        float v1 = fmaxf(acc1[mg][nt][rh * 2 + 1] + bias1, 0.f);
                        float w0 = v0 - __half2float(__float2half_rn(v0));
                        float w1v = v1 - __half2float(__float2half_rn(v1));
                        uint32_t off = swz((uint32_t)(row0 + rh * 8), (uint32_t)col * 2);
                        *reinterpret_cast<uint32_t*>(sm + OFF_RH + off) = pkhf2(v0, v1);
                        *reinterpret_cast<uint32_t*>(sm + OFF_RL + off) = pkhf2(w0, w1v);
                    }
                }
            }
            __syncthreads();  // R(half) ready

            // ---- GEMM2 (3 passes): accG[half] += C' @ R ----
#pragma unroll 1
            for (int pass = 0; pass < 3; pass++) {
                uint32_t Ab = smb + (pass == 2 ? OFF_CL : OFF_CH);
                uint32_t Bb = smb + (pass == 1 ? OFF_RL : OFF_RH);
#pragma unroll
                for (int k0 = 0; k0 < 128; k0 += 16) {
                    uint32_t a[4], b[2][4];
                    ldsm4(a, Ab + swz(m2base + lr, k0 * 2 + lc));
#pragma unroll
                    for (int nt2 = 0; nt2 < 2; nt2++)
                        ldsm4t(b[nt2], Bb + swz(k0 + lr, (n2base + nt2 * 16) * 2 + lc));
#pragma unroll
                    for (int nt = 0; nt < 4; nt++)
                        mma_fp16(accG[half][nt], a, &b[nt >> 1][(nt & 1) * 2]);
                }
            }
            if (half == 0) __syncthreads();  // G2h0 done reading R -> h1 may overwrite
        }  // half
    }  // tile

    // ---- drain persistent accumulators ----
#pragma unroll
    for (int half = 0; half < 2; half++)
#pragma unroll
        for (int nt = 0; nt < 4; nt++) {
            int gr = m2base + qrow;
            int col = half * 128 + n2base + nt * 8 + qcol;
            atomicAdd(&g_CR[gr * D_HID + col], accG[half][nt][0]);
            atomicAdd(&g_CR[gr * D_HID + col + 1], accG[half][nt][1]);
            atomicAdd(&g_CR[(gr + 8) * D_HID + col], accG[half][nt][2]);
            atomicAdd(&g_CR[(gr + 8) * D_HID + col + 1], accG[half][nt][3]);
        }
}

// ---------- final: pooled = CR @ w2 + rowsum*b2, log_softmax ----------
__global__ void k_final(const float* __restrict__ w2, const float* __restrict__ b2,
                        float* __restrict__ out) {
    int g = blockIdx.x;
    int f = threadIdx.x;
    float v = g_rowsum[g] * b2[f];
    const float* cr = g_CR + g * D_HID;
#pragma unroll 8
    for (int k = 0; k < D_HID; k++) v += cr[k] * w2[k * D_FEAT + f];

    __shared__ float sh[D_FEAT];
    sh[f] = v;
    __syncthreads();
    for (int s = D_FEAT / 2; s > 0; s >>= 1) {
        if (f < s) sh[f] = fmaxf(sh[f], sh[f + s]);
        __syncthreads();
    }
    float m = sh[0];
    __syncthreads();
    sh[f] = expf(v - m);
    __syncthreads();
    for (int s = D_FEAT / 2; s > 0; s >>= 1) {
        if (f < s) sh[f] += sh[f + s];
        __syncthreads();
    }
    float lse = logf(sh[0]);
    out[g * D_FEAT + f] = v - m - lse;
}

extern "C" void kernel_launch(void* const* d_in, const int* in_sizes, int n_in,
                              void* d_out, int out_size) {
    const float* x = (const float*)d_in[0];
    const void* ei = d_in[1];
    const float* ew = (const float*)d_in[2];
    const void* batch = d_in[3];
    const float* w1 = (const float*)d_in[4];
    const float* b1 = (const float*)d_in[5];
    const float* w2 = (const float*)d_in[6];
    const float* b2 = (const float*)d_in[7];
    const float* pw = (const float*)d_in[8];
    float* out = (float*)d_out;

    cudaFuncSetAttribute(k_fused, cudaFuncAttributeMaxDynamicSharedMemorySize, SMEM_TOTAL);

    k_detect<<<1, 256>>>((const unsigned int*)ei);
    k_prep<<<(N_NODES + 255) / 256, 256>>>(batch, pw);
    k_prepW<<<128, 256>>>(w1);
    k_zeroC<<<1024, 256>>>();
    k_edges<<<4096, 256>>>(ei, ew, pw);
    k_fused<<<GRID_FUSED, THREADS_FUSED, SMEM_TOTAL>>>(x, b1, pw);
    k_final<<<NUM_GRAPHS, D_FEAT>>>(w2, b2, out);
}

// round 12
// speedup vs baseline: 1.5610x; 1.4286x over previous
#include <cuda_runtime.h>
#include <cuda_fp16.h>
#include <cstdint>

#define N_NODES 100000
#define N_EDGES 1600000
#define N_HOPS 3
#define D_FEAT 128
#define D_HID 256
#define NUM_GRAPHS 64
#define TM 128
#define NT_TILES ((N_NODES + TM - 1) / TM)   // 782
#define GRID_FUSED 148
#define THREADS_FUSED 512

// ---- dynamic smem layout (bytes) ----
#define OFF_B1 0                     // 1024  (b1 fp32)
#define OFF_X  1024                  // 32768 (X fp16 [128][128] swizzled)
#define OFF_R  (OFF_X + 32768)       // 32768 (R fp16, current half)
#define OFF_W  (OFF_R + 32768)       // 65536 (W fp16 image, both halves)
#define OFF_C  (OFF_W + 65536)       // 16384 (C' fp16 [64][128])
#define SMEM_TOTAL (OFF_C + 16384)   // 148480

// Scratch (device globals; no runtime allocation allowed)
__device__ __align__(16) float g_C[(size_t)N_NODES * NUM_GRAPHS];  // 25.6 MB
__device__ __align__(16) float g_CR[NUM_GRAPHS * D_HID];
__device__ float g_rowsum[NUM_GRAPHS];
__device__ int g_idx64;
__device__ unsigned char g_b8[N_NODES];
// W1 fp16 image, pre-swizzled: [half][k 128][n 128]
__device__ __align__(16) unsigned char g_W1img[65536];

// ---------------- helpers ----------------
__device__ __forceinline__ uint32_t smem_u32(const void* p) {
    uint32_t a;
    asm("{ .reg .u64 t; cvta.to.shared.u64 t, %1; cvt.u32.u64 %0, t; }" : "=r"(a) : "l"(p));
    return a;
}
// swizzled byte offset within a [rows][256B] tile; cb = byte col in [0,256)
__device__ __forceinline__ uint32_t swz(uint32_t r, uint32_t cb) {
    return r * 256u + (((cb) & ~15u) ^ ((r & 7u) << 4)) + (cb & 15u);
}
__device__ __forceinline__ void ldsm4(uint32_t* r, uint32_t addr) {
    asm volatile("ldmatrix.sync.aligned.m8n8.x4.shared.b16 {%0,%1,%2,%3}, [%4];"
                 : "=r"(r[0]), "=r"(r[1]), "=r"(r[2]), "=r"(r[3]) : "r"(addr));
}
__device__ __forceinline__ void ldsm4t(uint32_t* r, uint32_t addr) {
    asm volatile("ldmatrix.sync.aligned.m8n8.x4.trans.shared.b16 {%0,%1,%2,%3}, [%4];"
                 : "=r"(r[0]), "=r"(r[1]), "=r"(r[2]), "=r"(r[3]) : "r"(addr));
}
__device__ __forceinline__ void mma_fp16(float* c, const uint32_t* a, const uint32_t* b) {
    asm volatile("mma.sync.aligned.m16n8k16.row.col.f32.f16.f16.f32 "
                 "{%0,%1,%2,%3}, {%4,%5,%6,%7}, {%8,%9}, {%0,%1,%2,%3};"
                 : "+f"(c[0]), "+f"(c[1]), "+f"(c[2]), "+f"(c[3])
                 : "r"(a[0]), "r"(a[1]), "r"(a[2]), "r"(a[3]), "r"(b[0]), "r"(b[1]));
}
__device__ __forceinline__ uint32_t pkhf2(float a, float b) {
    __half2 t = __floats2half2_rn(a, b);
    return *reinterpret_cast<uint32_t*>(&t);
}
__device__ __forceinline__ int load_index(const void* p, long long i, int is64) {
    if (is64) return (int)((const long long*)p)[i];
    return ((const int*)p)[i];
}

// ---------- kernel: detect int width + zero accumulators ----------
__global__ void k_detect(const unsigned int* __restrict__ ei_words) {
    int t = threadIdx.x;
    if (t == 0) {
        unsigned int acc = 0;
#pragma unroll
        for (int i = 0; i < 64; i++) acc |= ei_words[2 * i + 1];
        g_idx64 = (acc == 0u) ? 1 : 0;
    }
    for (int i = t; i < NUM_GRAPHS * D_HID; i += 256) g_CR[i] = 0.f;
    if (t < NUM_GRAPHS) g_rowsum[t] = 0.f;
}

// ---------- batch -> uint8 + rowsum pw0 part (smem histogram) ----------
__global__ void k_prep(const void* __restrict__ batch, const float* __restrict__ prop_w) {
    __shared__ float h[NUM_GRAPHS];
    int t = threadIdx.x;
    if (t < NUM_GRAPHS) h[t] = 0.f;
    __syncthreads();
    int is64 = g_idx64;
    float pw0 = prop_w[0];
    int i = blockIdx.x * blockDim.x + t;
    if (i < N_NODES) {
        int g = load_index(batch, i, is64) & (NUM_GRAPHS - 1);
        g_b8[i] = (unsigned char)g;
        atomicAdd(&h[g], pw0);
    }
    __syncthreads();
    if (t < NUM_GRAPHS && h[t] != 0.f) atomicAdd(&g_rowsum[t], h[t]);
}

// W1 -> pre-swizzled fp16 image per half: layout [k][n] (B of GEMM1)
__global__ void k_prepW(const float* __restrict__ w1) {
    int idx = blockIdx.x * blockDim.x + threadIdx.x;  // 2*128*128
    if (idx >= 2 * 128 * 128) return;
    int half = idx >> 14;
    int k = (idx >> 7) & 127;
    int n = idx & 127;
    float v = w1[(size_t)k * D_HID + half * 128 + n];
    uint32_t off = swz((uint32_t)k, (uint32_t)n * 2);
    *reinterpret_cast<__half*>(g_W1img + half * 32768 + off) = __float2half_rn(v);
}

// ---------- zero C (must precede edge atomics) ----------
__global__ void k_zeroC() {
    size_t i = (size_t)blockIdx.x * blockDim.x + threadIdx.x;
    size_t stride = (size_t)gridDim.x * blockDim.x;
    float4 z = make_float4(0.f, 0.f, 0.f, 0.f);
    size_t n4 = (size_t)N_NODES * NUM_GRAPHS / 4;
    for (size_t j = i; j < n4; j += stride) reinterpret_cast<float4*>(g_C)[j] = z;
}

// ---------- edge scatter into C + rowsum edge part (smem histogram) ----------
__global__ void k_edges(const void* __restrict__ ei, const float* __restrict__ ew,
                        const float* __restrict__ prop_w) {
    __shared__ float h[NUM_GRAPHS];
    int t = threadIdx.x;
    if (t < NUM_GRAPHS) h[t] = 0.f;
    __syncthreads();
    float pw0 = prop_w[1], pw1 = prop_w[2], pw2 = prop_w[3];
    int is64 = g_idx64;
    const long long total = (long long)N_HOPS * N_EDGES;
    long long stride = (long long)gridDim.x * blockDim.x;
    for (long long idx = (long long)blockIdx.x * blockDim.x + t; idx < total;
         idx += stride) {
        int hop = (int)(idx / N_EDGES);
        long long r = idx - (long long)hop * N_EDGES;
        long long base = (long long)hop * 2 * N_EDGES;
        int s = load_index(ei, base + r, is64);
        int d = load_index(ei, base + N_EDGES + r, is64);
        s = min(max(s, 0), N_NODES - 1);
        d = min(max(d, 0), N_NODES - 1);
        float w = ew[(size_t)hop * N_EDGES + r];
        float pw = (hop == 0) ? pw0 : (hop == 1) ? pw1 : pw2;
        int g = g_b8[d];
        float val = pw * w;
        atomicAdd(&g_C[(size_t)s * NUM_GRAPHS + g], val);
        atomicAdd(&h[g], val);
    }
    __syncthreads();
    if (t < NUM_GRAPHS && h[t] != 0.f) atomicAdd(&g_rowsum[t], h[t]);
}

// ---------- fused mma.sync kernel: fp16 single-pass both GEMMs ----------
__global__ void __launch_bounds__(THREADS_FUSED, 1)
k_fused(const float* __restrict__ x, const float* __restrict__ b1,
        const float* __restrict__ prop_w) {
    extern __shared__ char sm[];
    const uint32_t smb = smem_u32(sm);
    float* sb1 = reinterpret_cast<float*>(sm + OFF_B1);

    const int t = threadIdx.x;
    const int lane = t & 31;
    const int w = t >> 5;  // 0..15
    const float pw0 = prop_w[0];

    if (t < 256) sb1[t] = b1[t];
    // stage W fp16 image (both halves, resident across tiles)
    {
        const uint4* src = reinterpret_cast<const uint4*>(g_W1img);
        uint4* dst = reinterpret_cast<uint4*>(sm + OFF_W);
#pragma unroll
        for (int i = 0; i < 8; i++) dst[t + i * THREADS_FUSED] = src[t + i * THREADS_FUSED];
    }

    // GEMM1: warp = m32 (nodes) x n32 (hid cols within half)
    const int m1base = (w & 3) * 32;
    const int n1base = (w >> 2) * 32;
    // GEMM2: warp = m16 (graphs) x n32 (hid cols within half)
    const int m2base = (w & 3) * 16;
    const int n2base = (w >> 2) * 32;

    const uint32_t lr = lane & 15;
    const uint32_t lc = (lane >> 4) * 16;
    const int qrow = lane >> 2;
    const int qcol = (lane & 3) * 2;

    float accG[2][4][4];  // [half][nt][reg] persistent
#pragma unroll
    for (int h = 0; h < 2; h++)
#pragma unroll
        for (int b = 0; b < 4; b++)
#pragma unroll
            for (int c = 0; c < 4; c++) accG[h][b][c] = 0.f;

    for (int tile = blockIdx.x; tile < NT_TILES; tile += gridDim.x) {
        __syncthreads();  // all prev-tile readers of X/C/R done
        // ---- stage X tile -> fp16 (swizzled), once per tile ----
        {
            int row = t >> 2;
            int c0 = (t & 3) * 32;
            int node = tile * TM + row;
            bool valid = node < N_NODES;
            const float* xr = x + (size_t)node * D_FEAT + c0;
#pragma unroll
            for (int i = 0; i < 8; i++) {
                float4 f = valid ? *reinterpret_cast<const float4*>(xr + i * 4)
                                 : make_float4(0.f, 0.f, 0.f, 0.f);
                uint2 hv = make_uint2(pkhf2(f.x, f.y), pkhf2(f.z, f.w));
                uint32_t off = swz((uint32_t)row, (uint32_t)(c0 + i * 4) * 2);
                *reinterpret_cast<uint2*>(sm + OFF_X + off) = hv;
            }
        }
        // ---- stage C' (transposed fp16), fold pw0 delta, once per tile ----
        {
            int node = t >> 2;
            int g0 = (t & 3) * 16;
            int gn = tile * TM + node;
            bool valid = gn < N_NODES;
            int gb = valid ? (int)g_b8[gn] : -1;
            const float* cr = g_C + (size_t)gn * NUM_GRAPHS + g0;
#pragma unroll
            for (int i = 0; i < 4; i++) {
                float4 f = valid ? *reinterpret_cast<const float4*>(cr + i * 4)
                                 : make_float4(0.f, 0.f, 0.f, 0.f);
#pragma unroll
                for (int j = 0; j < 4; j++) {
                    int g = g0 + i * 4 + j;
                    float v = ((const float*)&f)[j];
                    if (g == gb) v += pw0;
                    uint32_t off = swz((uint32_t)g, (uint32_t)node * 2);
                    *reinterpret_cast<__half*>(sm + OFF_C + off) = __float2half_rn(v);
                }
            }
        }
        __syncthreads();

#pragma unroll 1
        for (int half = 0; half < 2; half++) {
            // ---- GEMM1 (1 pass): acc1 = X @ W(half) ----
            float acc1[2][4][4];
#pragma unroll
            for (int a = 0; a < 2; a++)
#pragma unroll
                for (int b = 0; b < 4; b++)
#pragma unroll
                    for (int c = 0; c < 4; c++) acc1[a][b][c] = 0.f;
            {
                uint32_t Ab = smb + OFF_X;
                uint32_t Bb = smb + OFF_W + half * 32768;
#pragma unroll
                for (int k0 = 0; k0 < 128; k0 += 16) {
                    uint32_t a[2][4], b[2][4];
#pragma unroll
                    for (int mg = 0; mg < 2; mg++)
                        ldsm4(a[mg], Ab + swz(m1base + mg * 16 + lr, k0 * 2 + lc));
#pragma unroll
                    for (int nt2 = 0; nt2 < 2; nt2++)
                        ldsm4t(b[nt2], Bb + swz(k0 + lr, (n1base + nt2 * 16) * 2 + lc));
#pragma unroll
                    for (int mg = 0; mg < 2; mg++)
#pragma unroll
                        for (int nt = 0; nt < 4; nt++)
                            mma_fp16(acc1[mg][nt], a[mg], &b[nt >> 1][(nt & 1) * 2]);
                }
            }
            // ---- bias + relu -> R (fp16) ----
            // h0: prev-tile GEMM2-h1 R-readers passed loop-top sync;
            // h1: GEMM2-h0 R-readers passed the sync below.
#pragma unroll
            for (int mg = 0; mg < 2; mg++) {
                int row0 = m1base + mg * 16 + qrow;
#pragma unroll
                for (int nt = 0; nt < 4; nt++) {
                    int col = n1base + nt * 8 + qcol;
                    float bias0 = sb1[half * 128 + col];
                    float bias1 = sb1[half * 128 + col + 1];
#pragma unroll
                    for (int rh = 0; rh < 2; rh++) {
                        float v0 = fmaxf(acc1[mg][nt][rh * 2 + 0] + bias0, 0.f);
                        float v1 = fmaxf(acc1[mg][nt][rh * 2 + 1] + bias1, 0.f);
                        uint32_t off = swz((uint32_t)(row0 + rh * 8), (uint32_t)col * 2);
                        *reinterpret_cast<uint32_t*>(sm + OFF_R + off) = pkhf2(v0, v1);
                    }
                }
            }
            __syncthreads();  // R(half) ready

            // ---- GEMM2 (1 pass): accG[half] += C' @ R ----
            {
                uint32_t Ab = smb + OFF_C;
                uint32_t Bb = smb + OFF_R;
#pragma unroll
                for (int k0 = 0; k0 < 128; k0 += 16) {
                    uint32_t a[4], b[2][4];
                    ldsm4(a, Ab + swz(m2base + lr, k0 * 2 + lc));
#pragma unroll
                    for (int nt2 = 0; nt2 < 2; nt2++)
                        ldsm4t(b[nt2], Bb + swz(k0 + lr, (n2base + nt2 * 16) * 2 + lc));
#pragma unroll
                    for (int nt = 0; nt < 4; nt++)
                        mma_fp16(accG[half][nt], a, &b[nt >> 1][(nt & 1) * 2]);
                }
            }
            if (half == 0) __syncthreads();  // GEMM2-h0 done reading R
        }  // half
    }  // tile

    // ---- drain persistent accumulators ----
#pragma unroll
    for (int half = 0; half < 2; half++)
#pragma unroll
        for (int nt = 0; nt < 4; nt++) {
            int gr = m2base + qrow;
            int col = half * 128 + n2base + nt * 8 + qcol;
            atomicAdd(&g_CR[gr * D_HID + col], accG[half][nt][0]);
            atomicAdd(&g_CR[gr * D_HID + col + 1], accG[half][nt][1]);
            atomicAdd(&g_CR[(gr + 8) * D_HID + col], accG[half][nt][2]);
            atomicAdd(&g_CR[(gr + 8) * D_HID + col + 1], accG[half][nt][3]);
        }
}

// ---------- final: pooled = CR @ w2 + rowsum*b2, log_softmax ----------
__global__ void k_final(const float* __restrict__ w2, const float* __restrict__ b2,
                        float* __restrict__ out) {
    int g = blockIdx.x;
    int f = threadIdx.x;
    float v = g_rowsum[g] * b2[f];
    const float* cr = g_CR + g * D_HID;
#pragma unroll 8
    for (int k = 0; k < D_HID; k++) v += cr[k] * w2[k * D_FEAT + f];

    __shared__ float sh[D_FEAT];
    sh[f] = v;
    __syncthreads();
    for (int s = D_FEAT / 2; s > 0; s >>= 1) {
        if (f < s) sh[f] = fmaxf(sh[f], sh[f + s]);
        __syncthreads();
    }
    float m = sh[0];
    __syncthreads();
    sh[f] = expf(v - m);
    __syncthreads();
    for (int s = D_FEAT / 2; s > 0; s >>= 1) {
        if (f < s) sh[f] += sh[f + s];
        __syncthreads();
    }
    float lse = logf(sh[0]);
    out[g * D_FEAT + f] = v - m - lse;
}

extern "C" void kernel_launch(void* const* d_in, const int* in_sizes, int n_in,
                              void* d_out, int out_size) {
    const float* x = (const float*)d_in[0];
    const void* ei = d_in[1];
    const float* ew = (const float*)d_in[2];
    const void* batch = d_in[3];
    const float* w1 = (const float*)d_in[4];
    const float* b1 = (const float*)d_in[5];
    const float* w2 = (const float*)d_in[6];
    const float* b2 = (const float*)d_in[7];
    const float* pw = (const float*)d_in[8];
    float* out = (float*)d_out;

    cudaFuncSetAttribute(k_fused, cudaFuncAttributeMaxDynamicSharedMemorySize, SMEM_TOTAL);

    k_detect<<<1, 256>>>((const unsigned int*)ei);
    k_prep<<<(N_NODES + 255) / 256, 256>>>(batch, pw);
    k_prepW<<<128, 256>>>(w1);
    k_zeroC<<<2048, 256>>>();
    k_edges<<<4096, 256>>>(ei, ew, pw);
    k_fused<<<GRID_FUSED, THREADS_FUSED, SMEM_TOTAL>>>(x, b1, pw);
    k_final<<<NUM_GRAPHS, D_FEAT>>>(w2, b2, out);
}